// round 11
// baseline (speedup 1.0000x reference)
#include <cuda_runtime.h>
#include <cstdint>

#define BB 64
#define CH 128
#define HH 40
#define WW 96
#define NELEM (BB*CH*HH*WW)          // 31,457,280
#define WTOT  (4*5*9*128*128)        // 2,949,120

// Scratch: transposed weights [dir][iter][k][ci][co] and ping-pong y buffers.
__device__ float g_wt[WTOT];
__device__ float g_buf[2][NELEM];

// ---------------------------------------------------------------------------
// One-time weight transpose: w[(it*128+co)*128+ci)*9+k] -> g_wt[((d*5+it)*9+k)*128+ci)*128+co]
// ---------------------------------------------------------------------------
__global__ void transpose_w_kernel(const float* __restrict__ wd, const float* __restrict__ wu,
                                   const float* __restrict__ wr, const float* __restrict__ wl) {
    int tid = blockIdx.x * 256 + threadIdx.x;
    if (tid >= WTOT) return;
    int co = tid & 127;
    int ci = (tid >> 7) & 127;
    int q  = tid >> 14;          // (d*5+it)*9 + k
    int k  = q % 9;
    int r  = q / 9;              // d*5 + it
    int it = r % 5;
    int d  = r / 5;
    const float* w = (d == 0) ? wd : (d == 1) ? wu : (d == 2) ? wr : wl;
    g_wt[tid] = w[((size_t)(it * 128 + co) * 128 + ci) * 9 + k];
}

// ---------------------------------------------------------------------------
// Horizontal conv step (1x9 along W, roll along H): phases D and U.
// CTA per (b, h). smem: inP[128][104] (w-padded by 4), Wsh[64][128] (ci-chunked).
// Thread tile: 8 c_out (4 f32x2 pairs) x 6 w. 256 threads, 2 CTAs/SM.
// ---------------------------------------------------------------------------
#define SMEM_H ((128*104 + 64*128)*4)

__global__ __launch_bounds__(256, 2)
void step_h_kernel(const float* __restrict__ src_ext, float* __restrict__ dst_ext,
                   int src_sel, int dst_sel, int widx, int hshift) {
    const float* src = (src_sel >= 0) ? g_buf[src_sel] : src_ext;
    float*       dst = (dst_sel >= 0) ? g_buf[dst_sel] : dst_ext;
    const float* w9  = g_wt + (size_t)widx * 9 * 128 * 128;

    extern __shared__ float sm[];
    float* inP = sm;                 // [128][104], tap index = w + 4
    float* Wsh = sm + 128 * 104;     // [64][128]

    int b = blockIdx.y, h = blockIdx.x;
    int t = threadIdx.x;
    int hs = h + hshift; if (hs >= HH) hs -= HH;   // in_h = (h + shift) mod 40

    // Load rolled input row: y[b, ci, hs, :] for all ci (float4, coalesced)
    const float* srow = src + ((size_t)b * CH * HH + hs) * WW;
    for (int i = t; i < 128 * 24; i += 256) {
        int ci = i / 24, wv = i % 24;
        float4 v = *(const float4*)(srow + (size_t)ci * HH * WW + wv * 4);
        *(float4*)&inP[ci * 104 + 4 + wv * 4] = v;
    }
    {   // zero pads: 4 floats on each side of every ci row (256 float4 total)
        float4 z4 = make_float4(0.f, 0.f, 0.f, 0.f);
        int ci = t >> 1, side = t & 1;
        *(float4*)&inP[ci * 104 + (side ? 100 : 0)] = z4;
    }

    int tx = t & 15, ty = t >> 4;
    int co0 = tx * 8, w0 = ty * 6;

    unsigned long long acc[4][6];
#pragma unroll
    for (int j = 0; j < 4; ++j)
#pragma unroll
        for (int jj = 0; jj < 6; ++jj) acc[j][jj] = 0ull;

    for (int k = 0; k < 9; ++k) {
        for (int cc = 0; cc < 2; ++cc) {
            __syncthreads();   // protect inP (first iter) / Wsh reuse
            const float4* wsrc = (const float4*)(w9 + (size_t)(k * 128 + cc * 64) * 128);
            float4* wdst = (float4*)Wsh;
#pragma unroll
            for (int i = 0; i < 8; ++i) wdst[t + i * 256] = wsrc[t + i * 256];
            __syncthreads();

            const float* ibase = inP + cc * 64 * 104 + w0 + k;
            const float* wbase = Wsh + co0;
#pragma unroll 4
            for (int cil = 0; cil < 64; ++cil) {
                ulonglong2 a01 = *(const ulonglong2*)(wbase + cil * 128);      // co pairs 0,1
                ulonglong2 a23 = *(const ulonglong2*)(wbase + cil * 128 + 4);  // co pairs 2,3
                const float* ib = ibase + cil * 104;
#pragma unroll
                for (int jj = 0; jj < 6; ++jj) {
                    unsigned int bi = __float_as_uint(ib[jj]);
                    unsigned long long bb;
                    asm("mov.b64 %0, {%1, %1};" : "=l"(bb) : "r"(bi));
                    asm("fma.rn.f32x2 %0, %1, %2, %0;" : "+l"(acc[0][jj]) : "l"(a01.x), "l"(bb));
                    asm("fma.rn.f32x2 %0, %1, %2, %0;" : "+l"(acc[1][jj]) : "l"(a01.y), "l"(bb));
                    asm("fma.rn.f32x2 %0, %1, %2, %0;" : "+l"(acc[2][jj]) : "l"(a23.x), "l"(bb));
                    asm("fma.rn.f32x2 %0, %1, %2, %0;" : "+l"(acc[3][jj]) : "l"(a23.y), "l"(bb));
                }
            }
        }
    }

    // y_out = y + 2*relu(conv)
    size_t ob = (((size_t)b * CH + co0) * HH + h) * WW + w0;
#pragma unroll
    for (int j = 0; j < 4; ++j) {
#pragma unroll
        for (int jj = 0; jj < 6; ++jj) {
            unsigned int lo, hi;
            asm("mov.b64 {%0, %1}, %2;" : "=r"(lo), "=r"(hi) : "l"(acc[j][jj]));
            size_t i0 = ob + (size_t)(2 * j) * HH * WW + jj;
            size_t i1 = i0 + (size_t)HH * WW;
            dst[i0] = src[i0] + 2.0f * fmaxf(__uint_as_float(lo), 0.f);
            dst[i1] = src[i1] + 2.0f * fmaxf(__uint_as_float(hi), 0.f);
        }
    }
}

// ---------------------------------------------------------------------------
// Vertical conv step (9x1 along H, roll along W): phases R and L.
// CTA per (b, 4-wide w tile). smem: inP[64ci][48h][4w] (h-padded by 4, ci-chunked),
// Wsh[64][128]. Thread tile: 4 c_out x 5 h x one aligned w-pair (f32x2 lanes = w).
// 512 threads, 1 CTA/SM.
// ---------------------------------------------------------------------------
#define SMEM_V ((64*48*4 + 64*128)*4)

__global__ __launch_bounds__(512, 1)
void step_v_kernel(const float* __restrict__ src_ext, float* __restrict__ dst_ext,
                   int src_sel, int dst_sel, int widx, int wshift) {
    const float* src = (src_sel >= 0) ? g_buf[src_sel] : src_ext;
    float*       dst = (dst_sel >= 0) ? g_buf[dst_sel] : dst_ext;
    const float* w9  = g_wt + (size_t)widx * 9 * 128 * 128;

    extern __shared__ float sm[];
    float* inP = sm;                 // [64][48][4]
    float* Wsh = sm + 64 * 48 * 4;   // [64][128]

    int b  = blockIdx.y;
    int w0 = blockIdx.x * 4;
    int t  = threadIdx.x;
    int co_g = t & 31, h_g = (t >> 5) & 7, w_g = t >> 8;   // 32 x 8 x 2 = 512
    int co0 = co_g * 4, h0 = h_g * 5;

    int ws[4];
#pragma unroll
    for (int wl = 0; wl < 4; ++wl) {
        int v = w0 + wl + wshift;                           // in_w = (w + shift) mod 96
        ws[wl] = (v >= WW) ? v - WW : v;
    }

    unsigned long long acc[4][5];
#pragma unroll
    for (int j = 0; j < 4; ++j)
#pragma unroll
        for (int jj = 0; jj < 5; ++jj) acc[j][jj] = 0ull;

    for (int cc = 0; cc < 2; ++cc) {
        __syncthreads();   // protect inP reuse across ci-chunks
        // Load rolled input columns: y[b, ci, h, ws[wl]] (sector-coalesced over wl)
        const float* sb = src + ((size_t)b * CH + cc * 64) * HH * WW;
        for (int i = t; i < 64 * 40 * 4; i += 512) {
            int wl  = i & 3;
            int hh  = (i >> 2) % 40;
            int cil = i / 160;
            inP[(cil * 48 + 4 + hh) * 4 + wl] = sb[((size_t)cil * HH + hh) * WW + ws[wl]];
        }
        for (int i = t; i < 64 * 8 * 4; i += 512) {   // zero pads (h rows 0..3 and 44..47)
            int wl  = i & 3;
            int r   = (i >> 2) & 7;
            int cil = i >> 5;
            int hp  = (r < 4) ? r : (r + 40);
            inP[(cil * 48 + hp) * 4 + wl] = 0.f;
        }
        for (int k = 0; k < 9; ++k) {
            __syncthreads();   // inP ready (k==0) / protect Wsh before overwrite
            const float4* wsrc = (const float4*)(w9 + (size_t)(k * 128 + cc * 64) * 128);
            float4* wdst = (float4*)Wsh;
#pragma unroll
            for (int i = 0; i < 4; ++i) wdst[t + i * 512] = wsrc[t + i * 512];
            __syncthreads();

#pragma unroll 2
            for (int cil = 0; cil < 64; ++cil) {
                float4 a4 = *(const float4*)&Wsh[cil * 128 + co0];
                unsigned long long ap0, ap1, ap2, ap3;
                asm("mov.b64 %0, {%1, %1};" : "=l"(ap0) : "r"(__float_as_uint(a4.x)));
                asm("mov.b64 %0, {%1, %1};" : "=l"(ap1) : "r"(__float_as_uint(a4.y)));
                asm("mov.b64 %0, {%1, %1};" : "=l"(ap2) : "r"(__float_as_uint(a4.z)));
                asm("mov.b64 %0, {%1, %1};" : "=l"(ap3) : "r"(__float_as_uint(a4.w)));
                const float* ib = &inP[(cil * 48 + h0 + k) * 4 + w_g * 2];
#pragma unroll
                for (int jj = 0; jj < 5; ++jj) {
                    unsigned long long bb = *(const unsigned long long*)(ib + jj * 4);
                    asm("fma.rn.f32x2 %0, %1, %2, %0;" : "+l"(acc[0][jj]) : "l"(ap0), "l"(bb));
                    asm("fma.rn.f32x2 %0, %1, %2, %0;" : "+l"(acc[1][jj]) : "l"(ap1), "l"(bb));
                    asm("fma.rn.f32x2 %0, %1, %2, %0;" : "+l"(acc[2][jj]) : "l"(ap2), "l"(bb));
                    asm("fma.rn.f32x2 %0, %1, %2, %0;" : "+l"(acc[3][jj]) : "l"(ap3), "l"(bb));
                }
            }
        }
    }

    int wout = w0 + w_g * 2;
    size_t ob = (((size_t)b * CH + co0) * HH + h0) * WW + wout;
#pragma unroll
    for (int j = 0; j < 4; ++j) {
#pragma unroll
        for (int jj = 0; jj < 5; ++jj) {
            unsigned int lo, hi;
            asm("mov.b64 {%0, %1}, %2;" : "=r"(lo), "=r"(hi) : "l"(acc[j][jj]));
            size_t idx = ob + (size_t)j * HH * WW + (size_t)jj * WW;
            dst[idx]     = src[idx]     + 2.0f * fmaxf(__uint_as_float(lo), 0.f);
            dst[idx + 1] = src[idx + 1] + 2.0f * fmaxf(__uint_as_float(hi), 0.f);
        }
    }
}

// ---------------------------------------------------------------------------
// Launcher: weight transpose + 20 chained step kernels, ping-pong buffers.
// Graph-capturable: kernel launches only, no allocs/syncs/copies.
// ---------------------------------------------------------------------------
extern "C" void kernel_launch(void* const* d_in, const int* in_sizes, int n_in,
                              void* d_out, int out_size) {
    const float* x  = (const float*)d_in[0];
    const float* wd = (const float*)d_in[1];
    const float* wu = (const float*)d_in[2];
    const float* wr = (const float*)d_in[3];
    const float* wl = (const float*)d_in[4];
    float* out = (float*)d_out;

    cudaFuncSetAttribute(step_h_kernel, cudaFuncAttributeMaxDynamicSharedMemorySize, SMEM_H);
    cudaFuncSetAttribute(step_v_kernel, cudaFuncAttributeMaxDynamicSharedMemorySize, SMEM_V);

    transpose_w_kernel<<<(WTOT + 255) / 256, 256>>>(wd, wu, wr, wl);

    static const int offH[5] = {1, 2, 5, 10, 20};    // 40 >> (5-i)
    static const int offW[5] = {3, 6, 12, 24, 48};   // 96 >> (5-i)

    int cur_sel = -1;   // step 0 reads external x
    for (int s = 0; s < 20; ++s) {
        int dst_sel = (s == 19) ? -1 : (s & 1);      // final step writes d_out
        int dir = s / 5, it = s % 5;
        int widx = dir * 5 + it;
        if (dir < 2) {
            // D: in_h=(h+off)%40 ; U: in_h=(h-off)%40 == shift 40-off
            int shift = (dir == 0) ? offH[it] : HH - offH[it];
            step_h_kernel<<<dim3(HH, BB), 256, SMEM_H>>>(x, out, cur_sel, dst_sel, widx, shift);
        } else {
            // R: in_w=(w+off)%96 ; L: shift 96-off
            int shift = (dir == 2) ? offW[it] : WW - offW[it];
            step_v_kernel<<<dim3(WW / 4, BB), 512, SMEM_V>>>(x, out, cur_sel, dst_sel, widx, shift);
        }
        cur_sel = dst_sel;
    }
}

// round 13
// speedup vs baseline: 1.3546x; 1.3546x over previous
#include <cuda_runtime.h>
#include <cstdint>

#define BB 64
#define CH 128
#define HH 40
#define WW 96
#define NELEM (BB*CH*HH*WW)          // 31,457,280
#define WTOT  (4*5*9*128*128)        // 2,949,120

// Scratch: transposed weights [dir][iter][k][ci][co] and ping-pong y buffers.
__device__ float g_wt[WTOT];
__device__ float g_buf[2][NELEM];

#define FFMA2(acc, a, b) asm("fma.rn.f32x2 %0, %1, %2, %0;" : "+l"(acc) : "l"(a), "l"(b))
#define SPLAT(d, f)      asm("mov.b64 %0, {%1, %1};" : "=l"(d) : "r"(__float_as_uint(f)))

// Injective weight swizzle at float4 granularity: block g (8 float4s) shifts by g.
// write: d4 = c4 + (c4>>3); read base for co-group g (8 floats = 2 float4s):
// woff = 8*g + 4*(g>>2). Worst-case 2-way bank conflict on the 16-lane read.
__device__ __forceinline__ int wswz(int c4) { return c4 + (c4 >> 3); }

// ---------------------------------------------------------------------------
// One-time weight transpose: w[((it*128+co)*128+ci)*9+k] -> g_wt[(((d*5+it)*9+k)*128+ci)*128+co]
// ---------------------------------------------------------------------------
__global__ void transpose_w_kernel(const float* __restrict__ wd, const float* __restrict__ wu,
                                   const float* __restrict__ wr, const float* __restrict__ wl) {
    int tid = blockIdx.x * 256 + threadIdx.x;
    if (tid >= WTOT) return;
    int co = tid & 127;
    int ci = (tid >> 7) & 127;
    int q  = tid >> 14;          // (d*5+it)*9 + k
    int k  = q % 9;
    int r  = q / 9;              // d*5 + it
    int it = r % 5;
    int d  = r / 5;
    const float* w = (d == 0) ? wd : (d == 1) ? wu : (d == 2) ? wr : wl;
    g_wt[tid] = w[((size_t)(it * 128 + co) * 128 + ci) * 9 + k];
}

// ---------------------------------------------------------------------------
// Horizontal conv step (1x9 along W, roll along H): phases D and U.
// CTA per (b, h). 192 threads: tx(16)=8 co, ty(12)=8 w. k-innermost, ci chunked
// by 8 with swizzled Wsh[9][8][140]. Input splats bb[16] reused across 9 taps.
// Epilogue staged via smem for coalesced global RMW.
// ---------------------------------------------------------------------------
#define INP_H_F   (128*104)                     // 13,312 floats
#define WSH_ROWF  140
#define WSH_F     (72*WSH_ROWF)                 // 10,080 floats
#define SMEM_H    ((INP_H_F + WSH_F)*4)         // 93,568 bytes

__global__ __launch_bounds__(192, 2)
void step_h_kernel(const float* __restrict__ src_ext, float* __restrict__ dst_ext,
                   int src_sel, int dst_sel, int widx, int hshift) {
    const float* src = (src_sel >= 0) ? g_buf[src_sel] : src_ext;
    float*       dst = (dst_sel >= 0) ? g_buf[dst_sel] : dst_ext;
    const float* w9  = g_wt + (size_t)widx * 9 * 128 * 128;

    extern __shared__ float sm[];
    float* inP = sm;                 // [128][104], tap index p = w + 4
    float* Wsh = sm + INP_H_F;       // [72 rows = k*8+cil][140], co swizzled

    int b = blockIdx.y, h = blockIdx.x;
    int t = threadIdx.x;
    int hs = h + hshift; if (hs >= HH) hs -= HH;

    // Load rolled input row y[b, ci, hs, :] for all 128 ci (float4 coalesced).
    const float* srow = src + ((size_t)b * CH * HH + hs) * WW;
    for (int i = t; i < 128 * 24; i += 192) {
        int ci = i / 24, wv = i % 24;
        float4 v = *(const float4*)(srow + (size_t)ci * HH * WW + wv * 4);
        *(float4*)&inP[ci * 104 + 4 + wv * 4] = v;
    }
    {   // zero pads p 0..3 and 100..103 on every ci row
        float4 z4 = make_float4(0.f, 0.f, 0.f, 0.f);
        for (int i = t; i < 256; i += 192) {
            int ci = i >> 1, side = i & 1;
            *(float4*)&inP[ci * 104 + side * 100] = z4;
        }
    }

    int tx = t & 15, ty = t >> 4;          // tx: co group, ty: w group
    int co0 = tx * 8, w0 = ty * 8;
    int woff = 8 * tx + 4 * (tx >> 2);     // swizzled smem float offset of co0

    unsigned long long acc[4][8];
#pragma unroll
    for (int j = 0; j < 4; ++j)
#pragma unroll
        for (int jj = 0; jj < 8; ++jj) acc[j][jj] = 0ull;

    for (int ch = 0; ch < 16; ++ch) {      // 8 ci per chunk
        __syncthreads();                   // Wsh reusable / inP ready (ch==0)
        // Stage Wsh[k][cil][co-swizzled] for ci in [ch*8, ch*8+8)
        for (int i = t; i < 2304; i += 192) {
            int c4 = i & 31, rest = i >> 5;           // rest = k*8 + cil
            float4 v = *(const float4*)(w9 + ((size_t)((rest >> 3) * 128 + ch * 8 + (rest & 7))) * 128 + c4 * 4);
            *(float4*)&Wsh[rest * WSH_ROWF + wswz(c4) * 4] = v;
        }
        __syncthreads();

#pragma unroll 1
        for (int cil = 0; cil < 8; ++cil) {
            const float* ib = inP + (ch * 8 + cil) * 104 + w0;
            float4 q0 = *(const float4*)(ib);
            float4 q1 = *(const float4*)(ib + 4);
            float4 q2 = *(const float4*)(ib + 8);
            float4 q3 = *(const float4*)(ib + 12);
            unsigned long long bb[16];
            SPLAT(bb[0], q0.x);  SPLAT(bb[1], q0.y);  SPLAT(bb[2], q0.z);  SPLAT(bb[3], q0.w);
            SPLAT(bb[4], q1.x);  SPLAT(bb[5], q1.y);  SPLAT(bb[6], q1.z);  SPLAT(bb[7], q1.w);
            SPLAT(bb[8], q2.x);  SPLAT(bb[9], q2.y);  SPLAT(bb[10], q2.z); SPLAT(bb[11], q2.w);
            SPLAT(bb[12], q3.x); SPLAT(bb[13], q3.y); SPLAT(bb[14], q3.z); SPLAT(bb[15], q3.w);

            const float* wrow = Wsh + cil * WSH_ROWF + woff;
#pragma unroll
            for (int k = 0; k < 9; ++k) {
                ulonglong2 a01 = *(const ulonglong2*)(wrow + k * 8 * WSH_ROWF);
                ulonglong2 a23 = *(const ulonglong2*)(wrow + k * 8 * WSH_ROWF + 4);
#pragma unroll
                for (int jj = 0; jj < 8; ++jj) {
                    FFMA2(acc[0][jj], a01.x, bb[k + jj]);
                    FFMA2(acc[1][jj], a01.y, bb[k + jj]);
                    FFMA2(acc[2][jj], a23.x, bb[k + jj]);
                    FFMA2(acc[3][jj], a23.y, bb[k + jj]);
                }
            }
        }
    }

    // Stage 2*relu(conv) into smem [w][co] (stride 130), then coalesced RMW.
    __syncthreads();
    float* so = inP;                       // reuse: needs 96*130 = 12,480 floats
#pragma unroll
    for (int j = 0; j < 4; ++j) {
#pragma unroll
        for (int jj = 0; jj < 8; ++jj) {
            unsigned int lo, hi;
            asm("mov.b64 {%0, %1}, %2;" : "=r"(lo), "=r"(hi) : "l"(acc[j][jj]));
            float v0 = 2.0f * fmaxf(__uint_as_float(lo), 0.f);
            float v1 = 2.0f * fmaxf(__uint_as_float(hi), 0.f);
            *(float2*)&so[(w0 + jj) * 130 + co0 + 2 * j] = make_float2(v0, v1);
        }
    }
    __syncthreads();
    for (int i = t; i < 128 * 96; i += 192) {
        int w = i % 96, co = i / 96;
        size_t gi = (((size_t)b * CH + co) * HH + h) * WW + w;
        dst[gi] = src[gi] + so[w * 130 + co];
    }
}

// ---------------------------------------------------------------------------
// Vertical conv step (9x1 along H, roll along W): phases R and L.
// CTA per (b, 4-wide w tile). 256 threads: co_g(16)=8 co, h_g(8)=5 h, w_g(2)=w pair.
// ci halves (cc) + 8-ci chunks with swizzled Wsh; f32x2 lanes = adjacent w pair
// (LDS.64 input), weight splats reused across 5 h. Epilogue staged via smem,
// float4 global RMW.
// ---------------------------------------------------------------------------
#define INP_V_F   (64*48*4)                 // 12,288 floats
#define SMEM_V    ((INP_V_F + WSH_F)*4)     // 89,472 bytes

__global__ __launch_bounds__(256, 2)
void step_v_kernel(const float* __restrict__ src_ext, float* __restrict__ dst_ext,
                   int src_sel, int dst_sel, int widx, int wshift) {
    const float* src = (src_sel >= 0) ? g_buf[src_sel] : src_ext;
    float*       dst = (dst_sel >= 0) ? g_buf[dst_sel] : dst_ext;
    const float* w9  = g_wt + (size_t)widx * 9 * 128 * 128;

    extern __shared__ float sm[];
    float* inP = sm;                 // [64][48][4]  (h padded by 4 each side)
    float* Wsh = sm + INP_V_F;       // [72][140]

    int b  = blockIdx.y;
    int w0 = blockIdx.x * 4;
    int t  = threadIdx.x;
    int co_g = t & 15, h_g = (t >> 4) & 7, w_g = t >> 7;   // 16 x 8 x 2
    int co0 = co_g * 8, h0 = h_g * 5;
    int woff = 8 * co_g + 4 * (co_g >> 2);

    int ws[4];
#pragma unroll
    for (int wl = 0; wl < 4; ++wl) {
        int v = w0 + wl + wshift;
        ws[wl] = (v >= WW) ? v - WW : v;
    }

    unsigned long long acc[8][5];
#pragma unroll
    for (int c = 0; c < 8; ++c)
#pragma unroll
        for (int jj = 0; jj < 5; ++jj) acc[c][jj] = 0ull;

    for (int cc = 0; cc < 2; ++cc) {
        __syncthreads();               // inP reusable across cc halves
        const float* sb = src + ((size_t)b * CH + cc * 64) * HH * WW;
        for (int i = t; i < 64 * 40 * 4; i += 256) {
            int wl  = i & 3;
            int hh  = (i >> 2) % 40;
            int cil = i / 160;
            inP[(cil * 48 + 4 + hh) * 4 + wl] = sb[((size_t)cil * HH + hh) * WW + ws[wl]];
        }
        for (int i = t; i < 64 * 8 * 4; i += 256) {   // zero pads p 0..3, 44..47
            int wl  = i & 3;
            int r   = (i >> 2) & 7;
            int cil = i >> 5;
            int hp  = (r < 4) ? r : (r + 40);
            inP[(cil * 48 + hp) * 4 + wl] = 0.f;
        }

        for (int ch = 0; ch < 8; ++ch) {
            __syncthreads();           // Wsh reusable / inP ready (ch==0)
            for (int i = t; i < 2304; i += 256) {
                int c4 = i & 31, rest = i >> 5;       // rest = k*8 + cil
                float4 v = *(const float4*)(w9 + ((size_t)((rest >> 3) * 128 + cc * 64 + ch * 8 + (rest & 7))) * 128 + c4 * 4);
                *(float4*)&Wsh[rest * WSH_ROWF + wswz(c4) * 4] = v;
            }
            __syncthreads();

#pragma unroll 1
            for (int cil = 0; cil < 8; ++cil) {
                int ci_h = ch * 8 + cil;
                const float* wrow = Wsh + cil * WSH_ROWF + woff;
                const float* irow = inP + (ci_h * 48 + h0) * 4 + w_g * 2;
#pragma unroll
                for (int k = 0; k < 9; ++k) {
                    float4 wa = *(const float4*)(wrow + k * 8 * WSH_ROWF);
                    float4 wb = *(const float4*)(wrow + k * 8 * WSH_ROWF + 4);
                    unsigned long long ip[5];
#pragma unroll
                    for (int jj = 0; jj < 5; ++jj)
                        ip[jj] = *(const unsigned long long*)(irow + (k + jj) * 4);
                    unsigned long long s0, s1, s2, s3, s4, s5, s6, s7;
                    SPLAT(s0, wa.x); SPLAT(s1, wa.y); SPLAT(s2, wa.z); SPLAT(s3, wa.w);
                    SPLAT(s4, wb.x); SPLAT(s5, wb.y); SPLAT(s6, wb.z); SPLAT(s7, wb.w);
#pragma unroll
                    for (int jj = 0; jj < 5; ++jj) {
                        FFMA2(acc[0][jj], s0, ip[jj]);
                        FFMA2(acc[1][jj], s1, ip[jj]);
                        FFMA2(acc[2][jj], s2, ip[jj]);
                        FFMA2(acc[3][jj], s3, ip[jj]);
                        FFMA2(acc[4][jj], s4, ip[jj]);
                        FFMA2(acc[5][jj], s5, ip[jj]);
                        FFMA2(acc[6][jj], s6, ip[jj]);
                        FFMA2(acc[7][jj], s7, ip[jj]);
                    }
                }
            }
        }
    }

    // Stage 2*relu(conv) into smem [h][co][4w], then float4 global RMW.
    __syncthreads();
    float* so = sm;                    // needs 40*128*4 = 20,480 <= 22,368 floats
#pragma unroll
    for (int c = 0; c < 8; ++c) {
#pragma unroll
        for (int jj = 0; jj < 5; ++jj) {
            unsigned int lo, hi;
            asm("mov.b64 {%0, %1}, %2;" : "=r"(lo), "=r"(hi) : "l"(acc[c][jj]));
            float v0 = 2.0f * fmaxf(__uint_as_float(lo), 0.f);
            float v1 = 2.0f * fmaxf(__uint_as_float(hi), 0.f);
            *(float2*)&so[((h0 + jj) * 128 + co0 + c) * 4 + w_g * 2] = make_float2(v0, v1);
        }
    }
    __syncthreads();
    for (int i = t; i < 40 * 128; i += 256) {
        int hh = i >> 7, co = i & 127;
        float4 sv = *(const float4*)&so[i * 4];
        size_t gi = (((size_t)b * CH + co) * HH + hh) * WW + w0;
        float4 s4 = *(const float4*)(src + gi);
        float4 o4;
        o4.x = s4.x + sv.x; o4.y = s4.y + sv.y; o4.z = s4.z + sv.z; o4.w = s4.w + sv.w;
        *(float4*)(dst + gi) = o4;
    }
}

// ---------------------------------------------------------------------------
// Launcher: weight transpose + 20 chained step kernels, ping-pong buffers.
// Graph-capturable: kernel launches only.
// ---------------------------------------------------------------------------
extern "C" void kernel_launch(void* const* d_in, const int* in_sizes, int n_in,
                              void* d_out, int out_size) {
    const float* x  = (const float*)d_in[0];
    const float* wd = (const float*)d_in[1];
    const float* wu = (const float*)d_in[2];
    const float* wr = (const float*)d_in[3];
    const float* wl = (const float*)d_in[4];
    float* out = (float*)d_out;

    cudaFuncSetAttribute(step_h_kernel, cudaFuncAttributeMaxDynamicSharedMemorySize, SMEM_H);
    cudaFuncSetAttribute(step_v_kernel, cudaFuncAttributeMaxDynamicSharedMemorySize, SMEM_V);

    transpose_w_kernel<<<(WTOT + 255) / 256, 256>>>(wd, wu, wr, wl);

    static const int offH[5] = {1, 2, 5, 10, 20};    // 40 >> (5-i)
    static const int offW[5] = {3, 6, 12, 24, 48};   // 96 >> (5-i)

    int cur_sel = -1;   // step 0 reads external x
    for (int s = 0; s < 20; ++s) {
        int dst_sel = (s == 19) ? -1 : (s & 1);      // final step writes d_out
        int dir = s / 5, it = s % 5;
        int widx = dir * 5 + it;
        if (dir < 2) {
            int shift = (dir == 0) ? offH[it] : HH - offH[it];
            step_h_kernel<<<dim3(HH, BB), 192, SMEM_H>>>(x, out, cur_sel, dst_sel, widx, shift);
        } else {
            int shift = (dir == 2) ? offW[it] : WW - offW[it];
            step_v_kernel<<<dim3(WW / 4, BB), 256, SMEM_V>>>(x, out, cur_sel, dst_sel, widx, shift);
        }
        cur_sel = dst_sel;
    }
}